// round 7
// baseline (speedup 1.0000x reference)
#include <cuda_runtime.h>
#include <math.h>

#define B_    32
#define FBINS 128
#define TTOT  2400
#define HDIM  256
#define SEG_  24
#define SSEG  100
#define BS_   3200   // B_*SSEG

// ---------------- scratch (device globals) ----------------------------------
__device__ float g_xT[B_*TTOT*FBINS];      // (B, T, F) transposed input
__device__ float g_rec[B_*TTOT*FBINS];     // (B, T, F) reconstruction
__device__ float g_hA[BS_*HDIM];           // oe hidden ping
__device__ float g_hB[BS_*HDIM];           // oe hidden pong
__device__ float g_c[BS_*HDIM];            // oe cell -> c_seg
__device__ float g_xw_ie[BS_*1024];
__device__ float g_bot[B_*HDIM];           // bottleneck (final cell of ie)
__device__ float g_xw_id[B_*1024];
__device__ float g_dec[BS_*HDIM];          // inner-decoder hidden states (B,S,H)
__device__ float g_xw_od[BS_*512];
__device__ float g_h2A[BS_*FBINS];         // od hidden ping
__device__ float g_h2B[BS_*FBINS];         // od hidden pong
__device__ float g_c2[BS_*FBINS];          // od cell
// interleaved weights (col = 4*u + g, g in {i,f,g,o}) / fused biases
__device__ float g_oe_wT[(FBINS+HDIM)*1024];   // rows 0..127: WihT, 128..383: WhhT
__device__ float g_oe_b[1024];
__device__ float g_ie_wihT[HDIM*1024];
__device__ float g_ie_whhI[HDIM*1024];
__device__ float g_ie_b[1024];
__device__ float g_id_wihT[HDIM*1024];
__device__ float g_id_whhI[HDIM*1024];
__device__ float g_id_b[1024];
__device__ float g_od_wihT[HDIM*512];
__device__ float g_od_whhT[FBINS*512];
__device__ float g_od_b[512];

__device__ __forceinline__ float sigf(float x) { return 1.0f / (1.0f + expf(-x)); }

// ---- packed f32x2 helpers ---------------------------------------------------
__device__ __forceinline__ unsigned long long dup2(unsigned int x) {
    unsigned long long d;
    asm("mov.b64 %0, {%1, %1};" : "=l"(d) : "r"(x));
    return d;
}
__device__ __forceinline__ void ffma2(unsigned long long& d, unsigned long long a, unsigned long long b) {
    asm("fma.rn.f32x2 %0, %1, %2, %0;" : "+l"(d) : "l"(a), "l"(b));
}
__device__ __forceinline__ float2 upk2(unsigned long long v) {
    unsigned int lo, hi;
    asm("mov.b64 {%0, %1}, %2;" : "=r"(lo), "=r"(hi) : "l"(v));
    return make_float2(__uint_as_float(lo), __uint_as_float(hi));
}

// ---------------- batched tiled transpose: src (batch, R, C) -> dst (batch, C, R)
__global__ void btrans(float* __restrict__ dst, const float* __restrict__ src, int R, int C) {
    __shared__ float tile[32][33];
    int b  = blockIdx.z;
    int c0 = blockIdx.x * 32, r0 = blockIdx.y * 32;
    const float* s = src + (size_t)b * R * C;
    float*       d = dst + (size_t)b * R * C;
    int tx = threadIdx.x, ty = threadIdx.y;   // 32 x 8
    #pragma unroll
    for (int i = 0; i < 32; i += 8) {
        int r = r0 + ty + i, c = c0 + tx;
        if (r < R && c < C) tile[ty + i][tx] = s[r * C + c];
    }
    __syncthreads();
    #pragma unroll
    for (int i = 0; i < 32; i += 8) {
        int c = c0 + ty + i, r = r0 + tx;
        if (c < C && r < R) d[c * R + r] = tile[tx][ty + i];
    }
}

// ---- weight interleave pack: dst[k*(4U) + 4u+g] = src[(g*U+u)*K + k] --------
__global__ void pack_w(float* __restrict__ dst, const float* __restrict__ src, int U, int K) {
    int idx = blockIdx.x * blockDim.x + threadIdx.x;
    int n4 = 4 * U;
    if (idx >= K * n4) return;
    int col = idx % n4;
    int k   = idx / n4;
    int u = col >> 2, g = col & 3;
    dst[idx] = src[(size_t)(g * U + u) * K + k];
}

// ---- fused interleaved biases ----------------------------------------------
__global__ void pack_bias(const float* oe1, const float* oe2,
                          const float* ie1, const float* ie2,
                          const float* id1, const float* id2,
                          const float* od1, const float* od2,
                          float* oeb, float* ieb, float* idb, float* odb) {
    int i = blockIdx.x * blockDim.x + threadIdx.x;
    if (i < 1024) {
        int u = i >> 2, g = i & 3;
        int s = g * 256 + u;
        oeb[i] = oe1[s] + oe2[s];
        ieb[i] = ie1[s] + ie2[s];
        idb[i] = id1[s] + id2[s];
        if (i < 512) {
            int u2 = i >> 2, g2 = i & 3;
            int s2 = g2 * 128 + u2;
            odb[i] = od1[s2] + od2[s2];
        }
    }
}

// ---------------- gate GEMM (f32x2), optionally fused with the LSTM cell -----
// G[m][col] = base + sum_{k<K1} A1[m*lda1+k]*WT[k][col] + sum_{k<K2} A2[m*lda2+k]*WT[K1+k][col]
// base = Rm ? Rm[m][col] : (bias ? bias[col] : 0)
// Interleaved cols: col = 4u+g -> a 64-wide tile holds 16 full units, so the
// cell update runs in the epilogue (FUSED=true). h_out MUST NOT alias A1/A2
// (caller ping-pongs the hidden-state buffers).
template<bool FUSED>
__global__ void __launch_bounds__(256)
gemm_k(int M, int N,
       const float* __restrict__ A1, int lda1, int K1,
       const float* __restrict__ A2, int lda2, int K2,
       const float* __restrict__ WT,
       const float* __restrict__ bias,
       const float* __restrict__ Rm,
       float* __restrict__ G,
       float* __restrict__ c, float* __restrict__ h_out,
       float* __restrict__ rec, int rec_stride,
       int first) {
    __shared__ __align__(16) float As[16][68];   // As[k][row]
    __shared__ __align__(16) float Bs[16][64];
    const int tid = threadIdx.x;
    const int bn = blockIdx.x * 64;
    const int bm = blockIdx.y * 64;
    const int tx = tid & 15;
    const int ty = tid >> 4;
    const int ar = tid >> 2;          // A row within tile
    const int ak = (tid & 3) * 4;     // A k-offset
    const int brow = tid >> 4;        // B k row
    const int bcol = (tid & 15) * 4;  // B n offset

    unsigned long long acc[2][4];
    #pragma unroll
    for (int i = 0; i < 2; i++)
        #pragma unroll
        for (int j = 0; j < 4; j++) acc[i][j] = 0ULL;

    const int K = K1 + K2;
    for (int k0 = 0; k0 < K; k0 += 16) {
        int row = bm + ar;
        float4 av = make_float4(0.f, 0.f, 0.f, 0.f);
        if (row < M) {
            if (k0 < K1) av = *reinterpret_cast<const float4*>(A1 + (size_t)row * lda1 + k0 + ak);
            else         av = *reinterpret_cast<const float4*>(A2 + (size_t)row * lda2 + (k0 - K1) + ak);
        }
        As[ak + 0][ar] = av.x;
        As[ak + 1][ar] = av.y;
        As[ak + 2][ar] = av.z;
        As[ak + 3][ar] = av.w;
        *reinterpret_cast<float4*>(&Bs[brow][bcol]) =
            *reinterpret_cast<const float4*>(WT + (size_t)(k0 + brow) * N + bn + bcol);
        __syncthreads();
        #pragma unroll
        for (int k = 0; k < 16; ++k) {
            longlong2 a2v = *reinterpret_cast<const longlong2*>(&As[k][ty * 4]); // (r0,r1),(r2,r3)
            uint4 bv = *reinterpret_cast<const uint4*>(&Bs[k][tx * 4]);
            unsigned long long b0 = dup2(bv.x);
            unsigned long long b1 = dup2(bv.y);
            unsigned long long b2 = dup2(bv.z);
            unsigned long long b3 = dup2(bv.w);
            unsigned long long a01 = (unsigned long long)a2v.x;
            unsigned long long a23 = (unsigned long long)a2v.y;
            ffma2(acc[0][0], a01, b0); ffma2(acc[0][1], a01, b1);
            ffma2(acc[0][2], a01, b2); ffma2(acc[0][3], a01, b3);
            ffma2(acc[1][0], a23, b0); ffma2(acc[1][1], a23, b1);
            ffma2(acc[1][2], a23, b2); ffma2(acc[1][3], a23, b3);
        }
        __syncthreads();
    }

    // unpack accumulators: acc[ii][j] holds rows (ty*4+2ii, ty*4+2ii+1), gate j
    float2 f[2][4];
    #pragma unroll
    for (int i = 0; i < 2; i++)
        #pragma unroll
        for (int j = 0; j < 4; j++) f[i][j] = upk2(acc[i][j]);

    float4 bb = make_float4(0.f, 0.f, 0.f, 0.f);
    if (!Rm && bias) bb = *reinterpret_cast<const float4*>(bias + bn + tx * 4);

    #pragma unroll
    for (int ii = 0; ii < 2; ii++) {
        #pragma unroll
        for (int half = 0; half < 2; half++) {
            int row = bm + ty * 4 + ii * 2 + half;
            if (row >= M) continue;
            float g0 = half ? f[ii][0].y : f[ii][0].x;
            float g1 = half ? f[ii][1].y : f[ii][1].x;
            float g2 = half ? f[ii][2].y : f[ii][2].x;
            float g3 = half ? f[ii][3].y : f[ii][3].x;
            float4 base = bb;
            if (Rm) base = *reinterpret_cast<const float4*>(Rm + (size_t)row * N + bn + tx * 4);
            g0 += base.x; g1 += base.y; g2 += base.z; g3 += base.w;
            if (FUSED) {
                int Hd = N >> 2;
                int u = (bn >> 2) + tx;
                size_t idx = (size_t)row * Hd + u;
                float cold = first ? 0.0f : c[idx];
                float cc = sigf(g1) * cold + sigf(g0) * tanhf(g2);
                c[idx] = cc;
                float hh = sigf(g3) * tanhf(cc);
                h_out[idx] = hh;
                if (rec) rec[(size_t)row * rec_stride + u] = hh;
            } else {
                *reinterpret_cast<float4*>(G + (size_t)row * N + bn + tx * 4) =
                    make_float4(g0, g1, g2, g3);
            }
        }
    }
}

// ---------------- persistent inner LSTM (batch 32, 1 block per sequence) ----
// xw interleaved: row layout [u*4+g]; weights interleaved float4 per (k,u).
__global__ void __launch_bounds__(256)
inner_lstm(const float* __restrict__ xw, int xw_block_stride, int xw_step_stride,
           const float4* __restrict__ wp,
           float* __restrict__ out_c, float* __restrict__ out_h, int steps) {
    __shared__ float h[HDIM];
    int b = blockIdx.x;
    int u = threadIdx.x;
    float c = 0.0f;
    h[u] = 0.0f;
    __syncthreads();
    const float* xwb = xw + (size_t)b * xw_block_stride;
    for (int s = 0; s < steps; ++s) {
        float4 xg = *reinterpret_cast<const float4*>(xwb + (u << 2));
        float g0 = xg.x, g1 = xg.y, g2 = xg.z, g3 = xg.w;
        #pragma unroll 8
        for (int k = 0; k < HDIM; ++k) {
            float hk = h[k];
            float4 w = wp[(k << 8) + u];
            g0 += hk * w.x;
            g1 += hk * w.y;
            g2 += hk * w.z;
            g3 += hk * w.w;
        }
        float cc = sigf(g1) * c + sigf(g0) * tanhf(g2);
        c = cc;
        float hh = sigf(g3) * tanhf(cc);
        __syncthreads();
        h[u] = hh;
        __syncthreads();
        if (out_h) out_h[((size_t)b * steps + s) * HDIM + u] = hh;
        xwb += xw_step_stride;
    }
    if (out_c) out_c[b * HDIM + u] = c;
}

// ---------------- host orchestration ----------------------------------------
extern "C" void kernel_launch(void* const* d_in, const int* in_sizes, int n_in,
                              void* d_out, int out_size) {
    const float* inp    = (const float*)d_in[0];
    const float* oe_wih = (const float*)d_in[1];
    const float* oe_whh = (const float*)d_in[2];
    const float* oe_bih = (const float*)d_in[3];
    const float* oe_bhh = (const float*)d_in[4];
    const float* ie_wih = (const float*)d_in[5];
    const float* ie_whh = (const float*)d_in[6];
    const float* ie_bih = (const float*)d_in[7];
    const float* ie_bhh = (const float*)d_in[8];
    const float* id_wih = (const float*)d_in[9];
    const float* id_whh = (const float*)d_in[10];
    const float* id_bih = (const float*)d_in[11];
    const float* id_bhh = (const float*)d_in[12];
    const float* od_wih = (const float*)d_in[13];
    const float* od_whh = (const float*)d_in[14];
    const float* od_bih = (const float*)d_in[15];
    const float* od_bhh = (const float*)d_in[16];
    float* out = (float*)d_out;

    void* p;
    cudaGetSymbolAddress(&p, g_xT);      float* xT      = (float*)p;
    cudaGetSymbolAddress(&p, g_rec);     float* rec     = (float*)p;
    cudaGetSymbolAddress(&p, g_hA);      float* hA      = (float*)p;
    cudaGetSymbolAddress(&p, g_hB);      float* hB      = (float*)p;
    cudaGetSymbolAddress(&p, g_c);       float* c1      = (float*)p;
    cudaGetSymbolAddress(&p, g_xw_ie);   float* xw_ie   = (float*)p;
    cudaGetSymbolAddress(&p, g_bot);     float* bot     = (float*)p;
    cudaGetSymbolAddress(&p, g_xw_id);   float* xw_id   = (float*)p;
    cudaGetSymbolAddress(&p, g_dec);     float* decb    = (float*)p;
    cudaGetSymbolAddress(&p, g_xw_od);   float* xw_od   = (float*)p;
    cudaGetSymbolAddress(&p, g_h2A);     float* h2A     = (float*)p;
    cudaGetSymbolAddress(&p, g_h2B);     float* h2B     = (float*)p;
    cudaGetSymbolAddress(&p, g_c2);      float* c2      = (float*)p;
    cudaGetSymbolAddress(&p, g_oe_wT);   float* oe_wT   = (float*)p;
    cudaGetSymbolAddress(&p, g_oe_b);    float* oe_b    = (float*)p;
    cudaGetSymbolAddress(&p, g_ie_wihT); float* ie_wihT = (float*)p;
    cudaGetSymbolAddress(&p, g_ie_whhI); float* ie_whhI = (float*)p;
    cudaGetSymbolAddress(&p, g_ie_b);    float* ie_b    = (float*)p;
    cudaGetSymbolAddress(&p, g_id_wihT); float* id_wihT = (float*)p;
    cudaGetSymbolAddress(&p, g_id_whhI); float* id_whhI = (float*)p;
    cudaGetSymbolAddress(&p, g_id_b);    float* id_b    = (float*)p;
    cudaGetSymbolAddress(&p, g_od_wihT); float* od_wihT = (float*)p;
    cudaGetSymbolAddress(&p, g_od_whhT); float* od_whhT = (float*)p;
    cudaGetSymbolAddress(&p, g_od_b);    float* od_b    = (float*)p;

    dim3 tb(32, 8);

    // ---- prep: fused biases + interleaved weights
    pack_bias<<<4, 256>>>(oe_bih, oe_bhh, ie_bih, ie_bhh, id_bih, id_bhh,
                          od_bih, od_bhh, oe_b, ie_b, id_b, od_b);
    pack_w<<<512,  256>>>(oe_wT,              oe_wih, 256, 128);
    pack_w<<<1024, 256>>>(oe_wT + 128 * 1024, oe_whh, 256, 256);
    pack_w<<<1024, 256>>>(ie_wihT,            ie_wih, 256, 256);
    pack_w<<<1024, 256>>>(ie_whhI,            ie_whh, 256, 256);
    pack_w<<<1024, 256>>>(id_wihT,            id_wih, 256, 256);
    pack_w<<<1024, 256>>>(id_whhI,            id_whh, 256, 256);
    pack_w<<<512,  256>>>(od_wihT,            od_wih, 128, 256);
    pack_w<<<256,  256>>>(od_whhT,            od_whh, 128, 128);

    // ---- input transpose (B,F,T) -> (B,T,F)
    btrans<<<dim3(75, 4, B_), tb>>>(xT, inp, FBINS, TTOT);

    // ---- outer encoder: 24 fused GEMM+cell steps, state (3200,256)
    // Ping-pong hidden state: step t reads h[t&1], writes h[(t+1)&1].
    {
        float* hbuf[2] = { hA, hB };
        for (int t = 0; t < SEG_; ++t) {
            gemm_k<true><<<dim3(16, 50), 256>>>(BS_, 1024,
                                                xT + t * FBINS, SEG_ * FBINS, FBINS,
                                                hbuf[t & 1], HDIM, (t ? HDIM : 0),
                                                oe_wT, oe_b, nullptr,
                                                nullptr, c1, hbuf[(t + 1) & 1],
                                                nullptr, 0, t == 0);
        }
    }

    // ---- inner encoder: xw precompute + persistent 100-step LSTM -> bottleneck
    gemm_k<false><<<dim3(16, 50), 256>>>(BS_, 1024, c1, HDIM, HDIM,
                                         nullptr, 0, 0, ie_wihT, ie_b, nullptr,
                                         xw_ie, nullptr, nullptr, nullptr, 0, 0);
    inner_lstm<<<B_, 256>>>(xw_ie, SSEG * 1024, 1024, (const float4*)ie_whhI,
                            bot, nullptr, SSEG);

    // ---- inner decoder: constant input per step
    gemm_k<false><<<dim3(16, 1), 256>>>(B_, 1024, bot, HDIM, HDIM,
                                        nullptr, 0, 0, id_wihT, id_b, nullptr,
                                        xw_id, nullptr, nullptr, nullptr, 0, 0);
    inner_lstm<<<B_, 256>>>(xw_id, 1024, 0, (const float4*)id_whhI,
                            nullptr, decb, SSEG);

    // ---- outer decoder: xw once, then 24 fused steps (writes rec directly)
    gemm_k<false><<<dim3(8, 50), 256>>>(BS_, 512, decb, HDIM, HDIM,
                                        nullptr, 0, 0, od_wihT, od_b, nullptr,
                                        xw_od, nullptr, nullptr, nullptr, 0, 0);
    {
        float* hbuf[2] = { h2A, h2B };
        for (int t = 0; t < SEG_; ++t) {
            gemm_k<true><<<dim3(8, 50), 256>>>(BS_, 512,
                                               hbuf[t & 1], FBINS, (t ? FBINS : 0),
                                               nullptr, 0, 0,
                                               od_whhT, nullptr, xw_od,
                                               nullptr, c2, hbuf[(t + 1) & 1],
                                               rec + t * FBINS, SEG_ * FBINS, t == 0);
        }
    }

    // ---- final transpose (B,T,F) -> (B,F,T)
    btrans<<<dim3(4, 75, B_), tb>>>(out, rec, TTOT, FBINS);
}

// round 8
// speedup vs baseline: 1.5263x; 1.5263x over previous
#include <cuda_runtime.h>
#include <math.h>

#define B_    32
#define FBINS 128
#define TTOT  2400
#define HDIM  256
#define SEG_  24
#define SSEG  100
#define BS_   3200   // B_*SSEG

// ---------------- scratch (device globals) ----------------------------------
__device__ float g_xT[B_*TTOT*FBINS];      // (B, T, F) transposed input
__device__ float g_rec[B_*TTOT*FBINS];     // (B, T, F) reconstruction
__device__ float g_hA[BS_*HDIM];           // oe hidden ping
__device__ float g_hB[BS_*HDIM];           // oe hidden pong
__device__ float g_c[BS_*HDIM];            // oe cell -> c_seg
__device__ float g_xw_ie[BS_*1024];
__device__ float g_bot[B_*HDIM];           // bottleneck (final cell of ie)
__device__ float g_xw_id[B_*1024];
__device__ float g_dec[BS_*HDIM];          // inner-decoder hidden states (B,S,H)
__device__ float g_xw_od[BS_*512];
__device__ float g_h2A[BS_*FBINS];         // od hidden ping
__device__ float g_h2B[BS_*FBINS];         // od hidden pong
__device__ float g_c2[BS_*FBINS];          // od cell
// interleaved weights (col = 4*u + g, g in {i,f,g,o}) / fused biases
__device__ float g_oe_wT[(FBINS+HDIM)*1024];   // rows 0..127: WihT, 128..383: WhhT
__device__ float g_oe_b[1024];
__device__ float g_ie_wihT[HDIM*1024];
__device__ float g_ie_whhI[HDIM*1024];
__device__ float g_ie_b[1024];
__device__ float g_id_wihT[HDIM*1024];
__device__ float g_id_whhI[HDIM*1024];
__device__ float g_id_b[1024];
__device__ float g_od_wihT[HDIM*512];
__device__ float g_od_whhT[FBINS*512];
__device__ float g_od_b[512];

__device__ __forceinline__ float sigf(float x) { return 1.0f / (1.0f + __expf(-x)); }

// ---------------- batched tiled transpose: src (batch, R, C) -> dst (batch, C, R)
__global__ void btrans(float* __restrict__ dst, const float* __restrict__ src, int R, int C) {
    __shared__ float tile[32][33];
    int b  = blockIdx.z;
    int c0 = blockIdx.x * 32, r0 = blockIdx.y * 32;
    const float* s = src + (size_t)b * R * C;
    float*       d = dst + (size_t)b * R * C;
    int tx = threadIdx.x, ty = threadIdx.y;   // 32 x 8
    #pragma unroll
    for (int i = 0; i < 32; i += 8) {
        int r = r0 + ty + i, c = c0 + tx;
        if (r < R && c < C) tile[ty + i][tx] = s[r * C + c];
    }
    __syncthreads();
    #pragma unroll
    for (int i = 0; i < 32; i += 8) {
        int c = c0 + ty + i, r = r0 + tx;
        if (c < C && r < R) d[c * R + r] = tile[tx][ty + i];
    }
}

// ---- weight interleave pack: dst[k*(4U) + 4u+g] = src[(g*U+u)*K + k] --------
__global__ void pack_w(float* __restrict__ dst, const float* __restrict__ src, int U, int K) {
    int idx = blockIdx.x * blockDim.x + threadIdx.x;
    int n4 = 4 * U;
    if (idx >= K * n4) return;
    int col = idx % n4;
    int k   = idx / n4;
    int u = col >> 2, g = col & 3;
    dst[idx] = src[(size_t)(g * U + u) * K + k];
}

// ---- fused interleaved biases ----------------------------------------------
__global__ void pack_bias(const float* oe1, const float* oe2,
                          const float* ie1, const float* ie2,
                          const float* id1, const float* id2,
                          const float* od1, const float* od2,
                          float* oeb, float* ieb, float* idb, float* odb) {
    int i = blockIdx.x * blockDim.x + threadIdx.x;
    if (i < 1024) {
        int u = i >> 2, g = i & 3;
        int s = g * 256 + u;
        oeb[i] = oe1[s] + oe2[s];
        ieb[i] = ie1[s] + ie2[s];
        idb[i] = id1[s] + id2[s];
        if (i < 512) {
            int u2 = i >> 2, g2 = i & 3;
            int s2 = g2 * 128 + u2;
            odb[i] = od1[s2] + od2[s2];
        }
    }
}

// ---------------- gate GEMM, double-buffered, optionally fused LSTM cell -----
// G[m][col] = base + sum_{k<K1} A1[m*lda1+k]*WT[k][col] + sum_{k<K2} A2[m*lda2+k]*WT[K1+k][col]
// base = Rm ? Rm[m][col] : (bias ? bias[col] : 0)
// Tiles: BM=128, BN=64, BK=16, 256 threads, 8x4 per thread.
// Interleaved cols (col = 4u+g): each thread's 4 cols form one complete unit,
// so the cell update runs in the epilogue (FUSED=true). h_out must not alias
// A1/A2 (caller ping-pongs). K1 must be a multiple of 16 (or 0).
template<bool FUSED>
__global__ void __launch_bounds__(256)
gemm_k(int M, int N,
       const float* __restrict__ A1, int lda1, int K1,
       const float* __restrict__ A2, int lda2, int K2,
       const float* __restrict__ WT,
       const float* __restrict__ bias,
       const float* __restrict__ Rm,
       float* __restrict__ G,
       float* __restrict__ c, float* __restrict__ h_out,
       float* __restrict__ rec, int rec_stride,
       int first) {
    __shared__ __align__(16) float As[2][16][132];   // As[buf][k][m]
    __shared__ __align__(16) float Bs[2][16][64];
    const int tid = threadIdx.x;
    const int bn = blockIdx.x * 64;
    const int bm = blockIdx.y * 128;
    const int tx = tid & 15;          // n group: cols tx*4..tx*4+3
    const int ty = tid >> 4;          // m group: rows ty*8..ty*8+7
    const int ar = tid & 127;         // A load row
    const int ak = (tid >> 7) << 3;   // A load k base: 0 or 8
    const int bk = tid >> 4;          // B load k row
    const int bc = (tid & 15) << 2;   // B load col

    const int K = K1 + K2;
    const int arow = bm + ar;
    const bool aok = arow < M;

    float acc[8][4];
    #pragma unroll
    for (int i = 0; i < 8; i++)
        #pragma unroll
        for (int j = 0; j < 4; j++) acc[i][j] = 0.0f;

    if (K > 0) {
        float4 pa0, pa1, pb;
        // prefetch stage 0 (k0 = 0); k = ak, both halves within one source
        pa0 = make_float4(0.f, 0.f, 0.f, 0.f); pa1 = pa0;
        if (aok) {
            const float* p = (ak < K1) ? (A1 + (size_t)arow * lda1 + ak)
                                       : (A2 + (size_t)arow * lda2 + (ak - K1));
            pa0 = *(const float4*)p;
            pa1 = *(const float4*)(p + 4);
        }
        pb = *(const float4*)(WT + (size_t)bk * N + bn + bc);

        As[0][ak + 0][ar] = pa0.x; As[0][ak + 1][ar] = pa0.y;
        As[0][ak + 2][ar] = pa0.z; As[0][ak + 3][ar] = pa0.w;
        As[0][ak + 4][ar] = pa1.x; As[0][ak + 5][ar] = pa1.y;
        As[0][ak + 6][ar] = pa1.z; As[0][ak + 7][ar] = pa1.w;
        *(float4*)&Bs[0][bk][bc] = pb;
        __syncthreads();

        int buf = 0;
        for (int k0 = 0; k0 < K; k0 += 16, buf ^= 1) {
            const bool more = (k0 + 16) < K;
            if (more) {
                int k = k0 + 16 + ak;
                pa0 = make_float4(0.f, 0.f, 0.f, 0.f); pa1 = pa0;
                if (aok) {
                    const float* p = (k < K1) ? (A1 + (size_t)arow * lda1 + k)
                                              : (A2 + (size_t)arow * lda2 + (k - K1));
                    pa0 = *(const float4*)p;
                    pa1 = *(const float4*)(p + 4);
                }
                pb = *(const float4*)(WT + (size_t)(k0 + 16 + bk) * N + bn + bc);
            }
            #pragma unroll
            for (int k = 0; k < 16; ++k) {
                float4 a0 = *(const float4*)&As[buf][k][ty * 8];
                float4 a1 = *(const float4*)&As[buf][k][ty * 8 + 4];
                float4 b  = *(const float4*)&Bs[buf][k][tx * 4];
                float av[8] = {a0.x, a0.y, a0.z, a0.w, a1.x, a1.y, a1.z, a1.w};
                #pragma unroll
                for (int r = 0; r < 8; ++r) {
                    acc[r][0] += av[r] * b.x;
                    acc[r][1] += av[r] * b.y;
                    acc[r][2] += av[r] * b.z;
                    acc[r][3] += av[r] * b.w;
                }
            }
            if (more) {
                int nb = buf ^ 1;
                As[nb][ak + 0][ar] = pa0.x; As[nb][ak + 1][ar] = pa0.y;
                As[nb][ak + 2][ar] = pa0.z; As[nb][ak + 3][ar] = pa0.w;
                As[nb][ak + 4][ar] = pa1.x; As[nb][ak + 5][ar] = pa1.y;
                As[nb][ak + 6][ar] = pa1.z; As[nb][ak + 7][ar] = pa1.w;
                *(float4*)&Bs[nb][bk][bc] = pb;
            }
            __syncthreads();
        }
    }

    // ---- epilogue
    float4 bb = make_float4(0.f, 0.f, 0.f, 0.f);
    if (!Rm && bias) bb = *(const float4*)(bias + bn + tx * 4);
    #pragma unroll
    for (int r = 0; r < 8; ++r) {
        int row = bm + ty * 8 + r;
        if (row >= M) continue;
        float g0 = acc[r][0], g1 = acc[r][1], g2 = acc[r][2], g3 = acc[r][3];
        if (Rm) {
            float4 bv = *(const float4*)(Rm + (size_t)row * N + bn + tx * 4);
            g0 += bv.x; g1 += bv.y; g2 += bv.z; g3 += bv.w;
        } else {
            g0 += bb.x; g1 += bb.y; g2 += bb.z; g3 += bb.w;
        }
        if (FUSED) {
            const int Hd = N >> 2;
            const int u = (bn >> 2) + tx;
            size_t idx = (size_t)row * Hd + u;
            float cold = first ? 0.0f : c[idx];
            float cc = sigf(g1) * cold + sigf(g0) * tanhf(g2);
            c[idx] = cc;
            float hh = sigf(g3) * tanhf(cc);
            h_out[idx] = hh;
            if (rec) rec[(size_t)row * rec_stride + u] = hh;
        } else {
            *(float4*)(G + (size_t)row * N + bn + tx * 4) = make_float4(g0, g1, g2, g3);
        }
    }
}

// ---------------- persistent inner LSTM (batch 32, 1 block per sequence) ----
// xw interleaved: row layout [u*4+g]; weights interleaved float4 per (k,u).
__global__ void __launch_bounds__(256)
inner_lstm(const float* __restrict__ xw, int xw_block_stride, int xw_step_stride,
           const float4* __restrict__ wp,
           float* __restrict__ out_c, float* __restrict__ out_h, int steps) {
    __shared__ float h[HDIM];
    int b = blockIdx.x;
    int u = threadIdx.x;
    float c = 0.0f;
    h[u] = 0.0f;
    __syncthreads();
    const float* xwb = xw + (size_t)b * xw_block_stride;
    for (int s = 0; s < steps; ++s) {
        float4 xg = *reinterpret_cast<const float4*>(xwb + (u << 2));
        float g0 = xg.x, g1 = xg.y, g2 = xg.z, g3 = xg.w;
        #pragma unroll 8
        for (int k = 0; k < HDIM; ++k) {
            float hk = h[k];
            float4 w = wp[(k << 8) + u];
            g0 += hk * w.x;
            g1 += hk * w.y;
            g2 += hk * w.z;
            g3 += hk * w.w;
        }
        float cc = sigf(g1) * c + sigf(g0) * tanhf(g2);
        c = cc;
        float hh = sigf(g3) * tanhf(cc);
        __syncthreads();
        h[u] = hh;
        __syncthreads();
        if (out_h) out_h[((size_t)b * steps + s) * HDIM + u] = hh;
        xwb += xw_step_stride;
    }
    if (out_c) out_c[b * HDIM + u] = c;
}

// ---------------- host orchestration ----------------------------------------
extern "C" void kernel_launch(void* const* d_in, const int* in_sizes, int n_in,
                              void* d_out, int out_size) {
    const float* inp    = (const float*)d_in[0];
    const float* oe_wih = (const float*)d_in[1];
    const float* oe_whh = (const float*)d_in[2];
    const float* oe_bih = (const float*)d_in[3];
    const float* oe_bhh = (const float*)d_in[4];
    const float* ie_wih = (const float*)d_in[5];
    const float* ie_whh = (const float*)d_in[6];
    const float* ie_bih = (const float*)d_in[7];
    const float* ie_bhh = (const float*)d_in[8];
    const float* id_wih = (const float*)d_in[9];
    const float* id_whh = (const float*)d_in[10];
    const float* id_bih = (const float*)d_in[11];
    const float* id_bhh = (const float*)d_in[12];
    const float* od_wih = (const float*)d_in[13];
    const float* od_whh = (const float*)d_in[14];
    const float* od_bih = (const float*)d_in[15];
    const float* od_bhh = (const float*)d_in[16];
    float* out = (float*)d_out;

    void* p;
    cudaGetSymbolAddress(&p, g_xT);      float* xT      = (float*)p;
    cudaGetSymbolAddress(&p, g_rec);     float* rec     = (float*)p;
    cudaGetSymbolAddress(&p, g_hA);      float* hA      = (float*)p;
    cudaGetSymbolAddress(&p, g_hB);      float* hB      = (float*)p;
    cudaGetSymbolAddress(&p, g_c);       float* c1      = (float*)p;
    cudaGetSymbolAddress(&p, g_xw_ie);   float* xw_ie   = (float*)p;
    cudaGetSymbolAddress(&p, g_bot);     float* bot     = (float*)p;
    cudaGetSymbolAddress(&p, g_xw_id);   float* xw_id   = (float*)p;
    cudaGetSymbolAddress(&p, g_dec);     float* decb    = (float*)p;
    cudaGetSymbolAddress(&p, g_xw_od);   float* xw_od   = (float*)p;
    cudaGetSymbolAddress(&p, g_h2A);     float* h2A     = (float*)p;
    cudaGetSymbolAddress(&p, g_h2B);     float* h2B     = (float*)p;
    cudaGetSymbolAddress(&p, g_c2);      float* c2      = (float*)p;
    cudaGetSymbolAddress(&p, g_oe_wT);   float* oe_wT   = (float*)p;
    cudaGetSymbolAddress(&p, g_oe_b);    float* oe_b    = (float*)p;
    cudaGetSymbolAddress(&p, g_ie_wihT); float* ie_wihT = (float*)p;
    cudaGetSymbolAddress(&p, g_ie_whhI); float* ie_whhI = (float*)p;
    cudaGetSymbolAddress(&p, g_ie_b);    float* ie_b    = (float*)p;
    cudaGetSymbolAddress(&p, g_id_wihT); float* id_wihT = (float*)p;
    cudaGetSymbolAddress(&p, g_id_whhI); float* id_whhI = (float*)p;
    cudaGetSymbolAddress(&p, g_id_b);    float* id_b    = (float*)p;
    cudaGetSymbolAddress(&p, g_od_wihT); float* od_wihT = (float*)p;
    cudaGetSymbolAddress(&p, g_od_whhT); float* od_whhT = (float*)p;
    cudaGetSymbolAddress(&p, g_od_b);    float* od_b    = (float*)p;

    dim3 tb(32, 8);

    // ---- prep: fused biases + interleaved weights
    pack_bias<<<4, 256>>>(oe_bih, oe_bhh, ie_bih, ie_bhh, id_bih, id_bhh,
                          od_bih, od_bhh, oe_b, ie_b, id_b, od_b);
    pack_w<<<512,  256>>>(oe_wT,              oe_wih, 256, 128);
    pack_w<<<1024, 256>>>(oe_wT + 128 * 1024, oe_whh, 256, 256);
    pack_w<<<1024, 256>>>(ie_wihT,            ie_wih, 256, 256);
    pack_w<<<1024, 256>>>(ie_whhI,            ie_whh, 256, 256);
    pack_w<<<1024, 256>>>(id_wihT,            id_wih, 256, 256);
    pack_w<<<1024, 256>>>(id_whhI,            id_whh, 256, 256);
    pack_w<<<512,  256>>>(od_wihT,            od_wih, 128, 256);
    pack_w<<<256,  256>>>(od_whhT,            od_whh, 128, 128);

    // ---- input transpose (B,F,T) -> (B,T,F)
    btrans<<<dim3(75, 4, B_), tb>>>(xT, inp, FBINS, TTOT);

    // ---- outer encoder: 24 fused GEMM+cell steps, state (3200,256)
    // Ping-pong hidden state: step t reads h[t&1], writes h[(t+1)&1].
    {
        float* hbuf[2] = { hA, hB };
        for (int t = 0; t < SEG_; ++t) {
            gemm_k<true><<<dim3(16, 25), 256>>>(BS_, 1024,
                                                xT + t * FBINS, SEG_ * FBINS, FBINS,
                                                hbuf[t & 1], HDIM, (t ? HDIM : 0),
                                                oe_wT, oe_b, nullptr,
                                                nullptr, c1, hbuf[(t + 1) & 1],
                                                nullptr, 0, t == 0);
        }
    }

    // ---- inner encoder: xw precompute + persistent 100-step LSTM -> bottleneck
    gemm_k<false><<<dim3(16, 25), 256>>>(BS_, 1024, c1, HDIM, HDIM,
                                         nullptr, 0, 0, ie_wihT, ie_b, nullptr,
                                         xw_ie, nullptr, nullptr, nullptr, 0, 0);
    inner_lstm<<<B_, 256>>>(xw_ie, SSEG * 1024, 1024, (const float4*)ie_whhI,
                            bot, nullptr, SSEG);

    // ---- inner decoder: constant input per step
    gemm_k<false><<<dim3(16, 1), 256>>>(B_, 1024, bot, HDIM, HDIM,
                                        nullptr, 0, 0, id_wihT, id_b, nullptr,
                                        xw_id, nullptr, nullptr, nullptr, 0, 0);
    inner_lstm<<<B_, 256>>>(xw_id, 1024, 0, (const float4*)id_whhI,
                            nullptr, decb, SSEG);

    // ---- outer decoder: xw once, then 24 fused steps (writes rec directly)
    gemm_k<false><<<dim3(8, 25), 256>>>(BS_, 512, decb, HDIM, HDIM,
                                        nullptr, 0, 0, od_wihT, od_b, nullptr,
                                        xw_od, nullptr, nullptr, nullptr, 0, 0);
    {
        float* hbuf[2] = { h2A, h2B };
        for (int t = 0; t < SEG_; ++t) {
            gemm_k<true><<<dim3(8, 25), 256>>>(BS_, 512,
                                               hbuf[t & 1], FBINS, (t ? FBINS : 0),
                                               nullptr, 0, 0,
                                               od_whhT, nullptr, xw_od,
                                               nullptr, c2, hbuf[(t + 1) & 1],
                                               rec + t * FBINS, SEG_ * FBINS, t == 0);
        }
    }

    // ---- final transpose (B,T,F) -> (B,F,T)
    btrans<<<dim3(4, 75, B_), tb>>>(out, rec, TTOT, FBINS);
}